// round 8
// baseline (speedup 1.0000x reference)
#include <cuda_runtime.h>
#include <cstddef>
#include <cstdint>

// Problem constants (match reference)
#define BB 4
#define CC 256
#define HH 512
#define WW 512
#define NROIS 32
#define OUT 7

__device__ int4 g_boxes[NROIS];

// Decode ROI boxes once (handles int64-vs-int32 harness dtype ambiguity).
__global__ void decode_rois_kernel(const void* __restrict__ rois_raw) {
    int t = threadIdx.x;   // 0..31
    const long long* r64 = (const long long*)rois_raw;
    const int*       r32 = (const int*)rois_raw;
    long long p0 = r64[0], p1 = r64[1], p2 = r64[2], p3 = r64[3];
    bool is64 = (p0 >= 0 && p0 <= WW) && (p1 >= 0 && p1 <= HH) &&
                (p2 > p0 && p2 <= WW) && (p3 > p1 && p3 <= HH);
    int4 box;
    if (is64) {
        box = make_int4((int)r64[t * 4 + 0], (int)r64[t * 4 + 1],
                        (int)r64[t * 4 + 2], (int)r64[t * 4 + 3]);
    } else {
        box = make_int4(r32[t * 4 + 0], r32[t * 4 + 1],
                        r32[t * 4 + 2], r32[t * 4 + 3]);
    }
    g_boxes[t] = box;
}

// One CTA per (roi, b, c), 224 threads (7 warps).
// Phase A: warp g = row group g. Vertical reduction GMEM->registers via
//          LDG.128 float4 accumulators (no smem staging, no LDGSTS).
//          Lanes: laneA=lane&15 -> chunk, half=lane>>4 -> row parity;
//          halves combined with shfl_xor(16).
// Phase B: 49 threads sum <=9 column sums each from tiny smem array.
__global__ __launch_bounds__(224)
void roi_adaptive_pool_kernel(const float* __restrict__ x,
                              float* __restrict__ out)
{
    int bid = blockIdx.x;
    int c   = bid & (CC - 1);
    int t   = bid >> 8;           // / CC
    int b   = t & (BB - 1);
    int roi = t >> 2;             // / BB

    int4 box = g_boxes[roi];
    int x1 = box.x, y1 = box.y, x2 = box.z, y2 = box.w;

    int w  = x2 - x1;                  // 16..63
    int h  = y2 - y1;                  // 16..63
    int xa = x1 & ~3;                  // 16B-aligned row start
    int ox = x1 - xa;                  // 0..3
    int nc = (x2 - xa + 3) >> 2;       // float4 chunks per row (4..17)

    __shared__ float4 colsum4[OUT][17];   // 1904 B

    int warp  = threadIdx.x >> 5;      // 0..6 = row group
    int lane  = threadIdx.x & 31;
    int laneA = lane & 15;             // chunk index
    int half  = lane >> 4;             // row parity within group

    int hs = (warp * h) / OUT;
    int he = ((warp + 1) * h + OUT - 1) / OUT;   // he - hs <= 9

    const float* base = x + ((size_t)(b * CC + c)) * (HH * WW)
                          + (size_t)(y1 + hs) * WW + xa;

    bool doA = laneA < nc;
    bool doX = (nc > 16) && (laneA == 0);        // rare 17th chunk

    float4 acc  = make_float4(0.f, 0.f, 0.f, 0.f);
    float4 acc2 = make_float4(0.f, 0.f, 0.f, 0.f);

    const float4* p  = (const float4*)base + laneA + half * (WW / 4);
    const float4* p2 = (const float4*)base + 16    + half * (WW / 4);
    for (int r = hs + half; r < he; r += 2) {
        if (doA) {
            float4 v = __ldg(p);
            acc.x += v.x; acc.y += v.y; acc.z += v.z; acc.w += v.w;
        }
        if (doX) {
            float4 v = __ldg(p2);
            acc2.x += v.x; acc2.y += v.y; acc2.z += v.z; acc2.w += v.w;
        }
        p  += 2 * (WW / 4);
        p2 += 2 * (WW / 4);
    }

    // combine the two row-parity halves (all lanes converged)
    acc.x  += __shfl_xor_sync(0xffffffffu, acc.x,  16);
    acc.y  += __shfl_xor_sync(0xffffffffu, acc.y,  16);
    acc.z  += __shfl_xor_sync(0xffffffffu, acc.z,  16);
    acc.w  += __shfl_xor_sync(0xffffffffu, acc.w,  16);
    acc2.x += __shfl_xor_sync(0xffffffffu, acc2.x, 16);
    acc2.y += __shfl_xor_sync(0xffffffffu, acc2.y, 16);
    acc2.z += __shfl_xor_sync(0xffffffffu, acc2.z, 16);
    acc2.w += __shfl_xor_sync(0xffffffffu, acc2.w, 16);

    if (half == 0 && doA) colsum4[warp][laneA] = acc;
    if (half == 0 && doX) colsum4[warp][16]    = acc2;
    __syncthreads();

    // Phase B: one thread per output bin.
    int tb = threadIdx.x;
    if (tb < OUT * OUT) {
        int i = tb / OUT;
        int j = tb - i * OUT;
        int hs2 = (i * h) / OUT;
        int he2 = ((i + 1) * h + OUT - 1) / OUT;
        int ws  = (j * w) / OUT;
        int we  = ((j + 1) * w + OUT - 1) / OUT;

        const float* cs = (const float*)colsum4[i] + ox;
        float s = 0.0f;
        #pragma unroll 4
        for (int cc = ws; cc < we; ++cc)
            s += cs[cc];

        float area = (float)((he2 - hs2) * (we - ws));
        size_t oidx = ((((size_t)b * (NROIS * CC)) + (size_t)roi * CC + c)
                       * (OUT * OUT)) + tb;
        out[oidx] = s / area;
    }
}

extern "C" void kernel_launch(void* const* d_in, const int* in_sizes, int n_in,
                              void* d_out, int out_size)
{
    const float* x    = (const float*)d_in[0];
    const void*  rois = d_in[1];
    float*       out  = (float*)d_out;

    decode_rois_kernel<<<1, NROIS>>>(rois);
    roi_adaptive_pool_kernel<<<NROIS * BB * CC, 224>>>(x, out);
}

// round 9
// speedup vs baseline: 1.6114x; 1.6114x over previous
#include <cuda_runtime.h>
#include <cstddef>
#include <cstdint>

// Problem constants (match reference)
#define BB 4
#define CC 256
#define HH 512
#define WW 512
#define NROIS 32
#define OUT 7
#define TS 68        // smem tile row stride in floats (16B-aligned)
#define KP 4         // planes (channels) per CTA

__device__ int4 g_boxes[NROIS];

__device__ __forceinline__ void cp_async16(uint32_t smem_dst, const void* gmem_src) {
    asm volatile("cp.async.cg.shared.global [%0], [%1], 16;\n"
                 :: "r"(smem_dst), "l"(gmem_src));
}
__device__ __forceinline__ void cp_commit() {
    asm volatile("cp.async.commit_group;\n" ::: "memory");
}
template <int N>
__device__ __forceinline__ void cp_wait() {
    asm volatile("cp.async.wait_group %0;\n" :: "n"(N) : "memory");
}

// Decode ROI boxes once (handles int64-vs-int32 harness dtype ambiguity).
__global__ void decode_rois_kernel(const void* __restrict__ rois_raw) {
    int t = threadIdx.x;   // 0..31
    const long long* r64 = (const long long*)rois_raw;
    const int*       r32 = (const int*)rois_raw;
    long long p0 = r64[0], p1 = r64[1], p2 = r64[2], p3 = r64[3];
    bool is64 = (p0 >= 0 && p0 <= WW) && (p1 >= 0 && p1 <= HH) &&
                (p2 > p0 && p2 <= WW) && (p3 > p1 && p3 <= HH);
    int4 box;
    if (is64) {
        box = make_int4((int)r64[t * 4 + 0], (int)r64[t * 4 + 1],
                        (int)r64[t * 4 + 2], (int)r64[t * 4 + 3]);
    } else {
        box = make_int4(r32[t * 4 + 0], r32[t * 4 + 1],
                        r32[t * 4 + 2], r32[t * 4 + 3]);
    }
    g_boxes[t] = box;
}

// One CTA per (roi, b, c-group-of-4), 128 threads, double-buffered pipeline:
// stage plane k+1 with cp.async while reducing plane k from the other buffer.
__global__ __launch_bounds__(128)
void roi_adaptive_pool_kernel(const float* __restrict__ x,
                              float* __restrict__ out)
{
    int bid = blockIdx.x;
    int cg  = bid & (CC / KP - 1);    // 0..63
    int t   = bid >> 6;
    int b   = t & (BB - 1);
    int roi = t >> 2;

    int4 box = g_boxes[roi];
    int x1 = box.x, y1 = box.y, x2 = box.z, y2 = box.w;

    int w  = x2 - x1;                  // 16..63
    int h  = y2 - y1;                  // 16..63
    int xa = x1 & ~3;                  // 16B-aligned row start
    int ox = x1 - xa;                  // 0..3
    int nc = (x2 - xa + 3) >> 2;       // float4 chunks per row (4..17)

    __shared__ float tile[2][64 * TS]; // 2 x 17408 B

    int c0 = cg * KP;
    const float* plane0 = x + ((size_t)(b * CC + c0)) * (HH * WW);

    // ---- staging geometry (warp covers a row pair; all 32 lanes used) ----
    int lane  = threadIdx.x & 31;
    int warp  = threadIdx.x >> 5;
    int laneA = lane & 15;             // chunk index
    int half  = lane >> 4;             // row of the pair
    int ncm   = nc < 16 ? nc : 16;
    bool doA  = laneA < ncm;
    bool doX  = (nc > 16) && (laneA == 15);   // rare 17th chunk
    int r0    = 2 * warp + half;

    const char* gbase = (const char*)(plane0 + (size_t)(y1 + r0) * WW + xa)
                        + laneA * 16;
    uint32_t sbase[2];
    sbase[0] = (uint32_t)__cvta_generic_to_shared(tile[0])
               + (uint32_t)(r0 * TS + laneA * 4) * 4u;
    sbase[1] = (uint32_t)__cvta_generic_to_shared(tile[1])
               + (uint32_t)(r0 * TS + laneA * 4) * 4u;

    // ---- phase-2 geometry (hoisted; identical for all KP planes) ----
    int tb  = threadIdx.x;
    int bin = tb >> 1;
    if (bin > 48) bin = 48;            // keep warp 3 converged
    int p = tb & 1;
    int i = bin / 7;
    int j = bin - i * 7;
    int hs = (i * h) / OUT;
    int he = ((i + 1) * h + OUT - 1) / OUT;
    int ws = (j * w) / OUT;
    int we = ((j + 1) * w + OUT - 1) / OUT;
    int ncol = we - ws;
    float inv_area = 1.0f / (float)((he - hs) * ncol);
    bool writer = (p == 0) && (tb < 2 * OUT * OUT);
    size_t obase = (((size_t)b * (NROIS * CC)) + (size_t)roi * CC + c0)
                   * (OUT * OUT) + bin;
    int roff = (hs + p) * TS + ox + ws;

    // ---- stage plane k into buffer k&1 ----
    auto stage = [&](int k) {
        const char* gp = gbase + (size_t)k * (HH * WW * 4);
        uint32_t    dp = sbase[k & 1];
        for (int r = r0; r < h; r += 8) {
            if (doA) cp_async16(dp, gp);
            if (doX) cp_async16(dp + 16u, gp + 16);
            gp += 8 * WW * 4;
            dp += 8u * TS * 4u;
        }
        cp_commit();
    };

    stage(0);
    #pragma unroll
    for (int k = 0; k < KP; ++k) {
        if (k + 1 < KP) { stage(k + 1); cp_wait<1>(); }
        else            { cp_wait<0>(); }
        __syncthreads();

        // compute plane k from buffer k&1 (2 threads per bin, parity rows)
        const float* row = tile[k & 1] + roff;
        float s = 0.0f;
        for (int rr = hs + p; rr < he; rr += 2) {
            #pragma unroll 4
            for (int cc = 0; cc < ncol; ++cc)
                s += row[cc];
            row += 2 * TS;
        }
        s += __shfl_xor_sync(0xffffffffu, s, 1);
        if (writer)
            out[obase + (size_t)k * (OUT * OUT)] = s * inv_area;

        __syncthreads();   // buffer k&1 reused by stage(k+2) next iteration
    }
}

extern "C" void kernel_launch(void* const* d_in, const int* in_sizes, int n_in,
                              void* d_out, int out_size)
{
    const float* x    = (const float*)d_in[0];
    const void*  rois = d_in[1];
    float*       out  = (float*)d_out;

    decode_rois_kernel<<<1, NROIS>>>(rois);
    roi_adaptive_pool_kernel<<<NROIS * BB * (CC / KP), 128>>>(x, out);
}

// round 10
// speedup vs baseline: 1.6494x; 1.0236x over previous
#include <cuda_runtime.h>
#include <cstddef>
#include <cstdint>

// Problem constants (match reference)
#define BB 4
#define CC 256
#define HH 512
#define WW 512
#define NROIS 32
#define OUT 7
#define TS 68        // smem tile row stride in floats (16B-aligned)
#define KP 4         // planes (channels) per CTA
#define HR 32        // max rows per half-plane buffer

__device__ int4 g_boxes[NROIS];

__device__ __forceinline__ void cp_async16(uint32_t smem_dst, const void* gmem_src) {
    asm volatile("cp.async.cg.shared.global [%0], [%1], 16;\n"
                 :: "r"(smem_dst), "l"(gmem_src));
}
__device__ __forceinline__ void cp_commit() {
    asm volatile("cp.async.commit_group;\n" ::: "memory");
}
template <int N>
__device__ __forceinline__ void cp_wait() {
    asm volatile("cp.async.wait_group %0;\n" :: "n"(N) : "memory");
}

// Decode ROI boxes once (handles int64-vs-int32 harness dtype ambiguity).
__global__ void decode_rois_kernel(const void* __restrict__ rois_raw) {
    int t = threadIdx.x;   // 0..31
    const long long* r64 = (const long long*)rois_raw;
    const int*       r32 = (const int*)rois_raw;
    long long p0 = r64[0], p1 = r64[1], p2 = r64[2], p3 = r64[3];
    bool is64 = (p0 >= 0 && p0 <= WW) && (p1 >= 0 && p1 <= HH) &&
                (p2 > p0 && p2 <= WW) && (p3 > p1 && p3 <= HH);
    int4 box;
    if (is64) {
        box = make_int4((int)r64[t * 4 + 0], (int)r64[t * 4 + 1],
                        (int)r64[t * 4 + 2], (int)r64[t * 4 + 3]);
    } else {
        box = make_int4(r32[t * 4 + 0], r32[t * 4 + 1],
                        r32[t * 4 + 2], r32[t * 4 + 3]);
    }
    g_boxes[t] = box;
}

// One CTA per (roi, b, c-group-of-4), 128 threads.
// Pipeline over 2*KP half-plane stages with two 32-row smem buffers (17.4 KB
// total -> ~2x the resident CTAs of the full-tile version). Bin partial sums
// accumulate in registers across the two halves of each plane.
__global__ __launch_bounds__(128)
void roi_adaptive_pool_kernel(const float* __restrict__ x,
                              float* __restrict__ out)
{
    int bid = blockIdx.x;
    int cg  = bid & (CC / KP - 1);    // 0..63
    int t   = bid >> 6;
    int b   = t & (BB - 1);
    int roi = t >> 2;

    int4 box = g_boxes[roi];
    int x1 = box.x, y1 = box.y, x2 = box.z, y2 = box.w;

    int w  = x2 - x1;                  // 16..63
    int h  = y2 - y1;                  // 16..63
    int h0 = (h + 1) >> 1;             // balanced split, <= 32
    int xa = x1 & ~3;                  // 16B-aligned row start
    int ox = x1 - xa;                  // 0..3
    int nc = (x2 - xa + 3) >> 2;       // float4 chunks per row (4..17)

    __shared__ float tile[2][HR * TS]; // 2 x 8704 B = 17408 B

    int c0 = cg * KP;
    const float* plane0 = x + ((size_t)(b * CC + c0)) * (HH * WW);

    // ---- staging geometry (warp covers a row pair; all 32 lanes used) ----
    int lane  = threadIdx.x & 31;
    int warp  = threadIdx.x >> 5;
    int laneA = lane & 15;             // chunk index
    int half  = lane >> 4;             // row of the pair
    int ncm   = nc < 16 ? nc : 16;
    bool doA  = laneA < ncm;
    bool doX  = (nc > 16) && (laneA == 15);   // rare 17th chunk
    int r0    = 2 * warp + half;       // 0..7

    const char* gwarp = (const char*)(plane0 + (size_t)y1 * WW + xa)
                        + (size_t)r0 * (WW * 4) + laneA * 16;
    uint32_t sb[2];
    sb[0] = (uint32_t)__cvta_generic_to_shared(tile[0])
            + (uint32_t)(r0 * TS + laneA * 4) * 4u;
    sb[1] = (uint32_t)__cvta_generic_to_shared(tile[1])
            + (uint32_t)(r0 * TS + laneA * 4) * 4u;

    // ---- phase-2 geometry (hoisted; identical for all planes) ----
    int tb  = threadIdx.x;
    int bin = tb >> 1;
    if (bin > 48) bin = 48;            // keep warp 3 converged
    int p = tb & 1;
    int i = bin / 7;
    int j = bin - i * 7;
    int hs = (i * h) / OUT;
    int he = ((i + 1) * h + OUT - 1) / OUT;
    int ws = (j * w) / OUT;
    int we = ((j + 1) * w + OUT - 1) / OUT;
    int ncol = we - ws;
    float inv_area = 1.0f / (float)((he - hs) * ncol);
    bool writer = (p == 0) && (tb < 2 * OUT * OUT);
    size_t obase = (((size_t)b * (NROIS * CC)) + (size_t)roi * CC + c0)
                   * (OUT * OUT) + bin;
    int coff = ox + ws;

    // ---- stage half-plane: stage index st = 2*k + hh ----
    auto stage = [&](int st) {
        int k      = st >> 1;
        int hh     = st & 1;
        int rstart = hh ? h0 : 0;
        int rend   = hh ? h  : h0;
        const char* gp = gwarp + (size_t)k * (HH * WW * 4)
                               + (size_t)rstart * (WW * 4);
        uint32_t dp = sb[st & 1];
        for (int r = rstart + r0; r < rend; r += 8) {
            if (doA) cp_async16(dp, gp);
            if (doX) cp_async16(dp + 16u, gp + 16);
            gp += 8 * WW * 4;
            dp += 8u * TS * 4u;
        }
        cp_commit();
    };

    float acc = 0.0f;
    stage(0);
    #pragma unroll
    for (int st = 0; st < 2 * KP; ++st) {
        if (st + 1 < 2 * KP) { stage(st + 1); cp_wait<1>(); }
        else                 { cp_wait<0>(); }
        __syncthreads();

        int hh     = st & 1;
        int rstart = hh ? h0 : 0;
        int rend   = hh ? h  : h0;

        // this thread's bin rows (parity p) clipped to [rstart, rend)
        int rr = hs + p;
        if (rr < rstart) rr += (rstart - rr + 1) & ~1;   // keep parity
        int rlim = he < rend ? he : rend;

        const float* row = tile[st & 1] + (rr - rstart) * TS + coff;
        for (; rr < rlim; rr += 2) {
            #pragma unroll 4
            for (int cc = 0; cc < ncol; ++cc)
                acc += row[cc];
            row += 2 * TS;
        }

        if (hh) {   // plane complete: combine parity halves and write
            float s = acc + __shfl_xor_sync(0xffffffffu, acc, 1);
            if (writer)
                out[obase + (size_t)(st >> 1) * (OUT * OUT)] = s * inv_area;
            acc = 0.0f;
        }
        __syncthreads();   // buffer st&1 reused by stage(st+2)
    }
}

extern "C" void kernel_launch(void* const* d_in, const int* in_sizes, int n_in,
                              void* d_out, int out_size)
{
    const float* x    = (const float*)d_in[0];
    const void*  rois = d_in[1];
    float*       out  = (float*)d_out;

    decode_rois_kernel<<<1, NROIS>>>(rois);
    roi_adaptive_pool_kernel<<<NROIS * BB * (CC / KP), 128>>>(x, out);
}